// round 16
// baseline (speedup 1.0000x reference)
#include <cuda_runtime.h>
#include <cuda_fp16.h>

// ============================================================================
// DecomposableAttentionEncoder on GB300 (sm_103a), compute_103-safe.
// GEMMs via warp-level mma.sync fp16, two precision tiers:
//   SPLIT=1: x=hi+lo fp16; A@B ~= AhBh+AhBl+AlBh, fp32 acc (3 MMA)
//   SPLIT=0: pure fp16-hi, 1 MMA (GEMMs strictly downstream of all softmaxes)
// Tile 128(M)x64(N), 256 threads, K-chunk 64, 2-stage cp.async, 2 CTAs/SM,
// unconditional tail commit (r11 race fix). Warp grid 4x2 (r15, ldsm-balanced).
// r12/r13: symmetric self-scores + smem-staged coalesced mirror; fused,
//          staged transposed split outputs.
// r16: barrier-shadowed mainloop — per chunk: [wait,sync] -> s0/s1 load+mma ->
//      s2/s3 loads -> sync -> issue+commit -> s2/s3 mma. The cp.async burst
//      and barrier skew are hidden behind half a chunk of tensor work.
//      MMA order per element unchanged -> bit-identical numerics.
// ============================================================================

typedef long long ll;
typedef __half fp16;

// ---------------- static pools (element counts, fp16) ------------------------
#define E1 8388608LL            // 32*512*512
#define E2 33554432LL           // 32*512*2048
#define E3 16777216LL           // 32*1024*512
#define W1 262144LL
#define W2 524288LL
#define W3 1048576LL
#define O_IPH 0LL
#define O_IHH (O_IPH+E1)
#define O_IPL (O_IHH+E1)
#define O_IHL (O_IPL+E1)
#define O_PXH (O_IHL+E1)
#define O_HXH (O_PXH+E2)
#define O_PXL (O_HXH+E2)
#define O_HXL (O_PXL+E2)
#define O_PTH (O_HXL+E2)
#define O_HTH (O_PTH+E3)
#define O_PTL (O_HTH+E3)
#define O_HTL (O_PTL+E3)
#define O_FH  (O_HTL+E3)
#define O_GH  (O_FH+E1)
#define O_FL  (O_GH+E1)
#define O_GL  (O_FL+E1)
#define O_TH  (O_GL+E1)
#define O_TL  (O_TH+2*E1)
#define O_P1H (O_TL+2*E1)
#define O_P1L (O_P1H+2*E1)
#define O_WPYH (O_P1L+2*E1)
#define O_WPXH (O_WPYH+W1)
#define O_WPYL (O_WPXH+W1)
#define O_WPXL (O_WPYL+W1)
#define O_WS1H (O_WPXL+W1)
#define O_WS1L (O_WS1H+W1)
#define O_WS2H (O_WS1L+W1)
#define O_WS2L (O_WS2H+W1)
#define O_WA2H (O_WS2L+W1)
#define O_WA2L (O_WA2H+W1)
#define O_WC2H (O_WA2L+W1)
#define O_WC2L (O_WC2H+W1)
#define O_WA1H (O_WC2L+W1)
#define O_WA1L (O_WA1H+W2)
#define O_WC1H (O_WA1L+W2)
#define O_WC1L (O_WC1H+W3)
#define FP16_TOTAL (O_WC1L+W3)

__device__ fp16 g_fp16[FP16_TOTAL];
__device__ float g_fp[2 * E1 + 32768 + 16384 + 1024];   // SB|ST, RED, AGG, BB

// triangular super-tile tables (4x4 upper triangle incl. diagonal, 10 tiles)
__constant__ int c_smt[10] = {0, 0, 0, 0, 1, 1, 1, 2, 2, 3};
__constant__ int c_snt[10] = {0, 1, 2, 3, 1, 2, 3, 2, 3, 3};

// ---------------- PTX helpers -----------------------------------------------
__device__ __forceinline__ unsigned smem_u32(const void* p) {
    unsigned a;
    asm("{ .reg .u64 t; cvta.to.shared.u64 t, %1; cvt.u32.u64 %0, t; }"
        : "=r"(a) : "l"(p));
    return a;
}
__device__ __forceinline__ void cp16(unsigned dst, const void* src) {
    asm volatile("cp.async.cg.shared.global [%0], [%1], 16;"
                 ::"r"(dst), "l"(src) : "memory");
}
#define CP_COMMIT() asm volatile("cp.async.commit_group;" ::: "memory")
#define CP_WAIT1() asm volatile("cp.async.wait_group 1;" ::: "memory")

__device__ __forceinline__ void ldsm4(unsigned r[4], unsigned addr) {
    asm volatile("ldmatrix.sync.aligned.m8n8.x4.shared.b16 {%0,%1,%2,%3}, [%4];"
                 : "=r"(r[0]), "=r"(r[1]), "=r"(r[2]), "=r"(r[3]) : "r"(addr));
}
__device__ __forceinline__ void mma_f32(float c[4], const unsigned a[4],
                                        const unsigned b[2]) {
    asm volatile(
        "mma.sync.aligned.m16n8k16.row.col.f32.f16.f16.f32 "
        "{%0,%1,%2,%3}, {%4,%5,%6,%7}, {%8,%9}, {%0,%1,%2,%3};"
        : "+f"(c[0]), "+f"(c[1]), "+f"(c[2]), "+f"(c[3])
        : "r"(a[0]), "r"(a[1]), "r"(a[2]), "r"(a[3]), "r"(b[0]), "r"(b[1]));
}

// ---------------- HMMA GEMM (128x64 tile, occ 2, sym/fuse, staged) -----------
// C[M,N] = act( A @ B^T + bias (+dist relbias) ), 256 threads.
// Warp grid 4(M)x2(N): warp tile 32x32, ldsm-balanced.
template <int SPLIT>
__global__ void __launch_bounds__(256, 2)
tcgemm(const fp16* __restrict__ Ah, const fp16* __restrict__ Al, int lda, ll sA,
       const fp16* __restrict__ Bh, const fp16* __restrict__ Bl, int ldb, ll sB,
       float* Cf, fp16* Ch, fp16* Cl, int ldc, ll sC,
       fp16* ChT, fp16* ClT, ll sTz,
       const float* __restrict__ bias, ll sBias, int relu,
       const float* __restrict__ dist, int K, int bswap, int sym) {
    constexpr unsigned BOFF = SPLIT ? 32768u : 16384u;
    constexpr unsigned BSZ = 8192u;
    constexpr unsigned STG = SPLIT ? 49152u : 24576u;
    extern __shared__ char smarr[];
    const unsigned sb = smem_u32(smarr);
    const int tid = threadIdx.x, lane = tid & 31, wid = tid >> 5;
    const int wm = wid >> 1, wn = wid & 1;   // warp tile 32(M) x 32(N)
    int m0, n0;
    if (sym) {
        int t = blockIdx.x >> 1;
        m0 = c_smt[t] * 128;
        n0 = c_snt[t] * 128 + (blockIdx.x & 1) * 64;
    } else {
        m0 = blockIdx.y * 128;
        n0 = blockIdx.x * 64;
    }
    const int bz = bswap ? ((int)blockIdx.z ^ 32) : (int)blockIdx.z;
    Ah += (ll)blockIdx.z * sA;
    Bh += (ll)bz * sB;
    if (SPLIT) { Al += (ll)blockIdx.z * sA; Bl += (ll)bz * sB; }
    if (bias) bias += (ll)blockIdx.z * sBias;

    const int nc = K >> 6;

    unsigned aoff[2];
    int arw[2];
#pragma unroll
    for (int mt = 0; mt < 2; mt++) {
        int r = wm * 32 + mt * 16 + (lane & 15);
        aoff[mt] = r * 128;
        arw[mt] = r & 7;
    }
    unsigned boff[2];
    int brw[2];
#pragma unroll
    for (int g = 0; g < 2; g++) {
        int r = wn * 32 + g * 16 + (lane & 7) + (((lane >> 4) & 1) << 3);
        boff[g] = r * 128;
        brw[g] = r & 7;
    }
    const int achi = (lane >> 4) & 1;
    const int bchi = (lane >> 3) & 1;

    auto issue = [&](int c) {
        const int kc = c * 64;
        const unsigned st = sb + (c & 1) * STG;
#pragma unroll
        for (int i = 0; i < 4; i++) {
            int idx = tid + i * 256;
            int r = idx >> 3, ck = idx & 7;
            unsigned sw = (unsigned)(r * 128 + ((ck ^ (r & 7)) << 4));
            const ll ao = (ll)(m0 + r) * lda + kc + ck * 8;
            cp16(st + sw, Ah + ao);
            if (SPLIT) cp16(st + 16384 + sw, Al + ao);
        }
#pragma unroll
        for (int i = 0; i < 2; i++) {
            int idx = tid + i * 256;
            int r = idx >> 3, ck = idx & 7;
            unsigned sw = (unsigned)(r * 128 + ((ck ^ (r & 7)) << 4));
            const ll bo = (ll)(n0 + r) * ldb + kc + ck * 8;
            cp16(st + BOFF + sw, Bh + bo);
            if (SPLIT) cp16(st + BOFF + BSZ + sw, Bl + bo);
        }
    };

    // fragment loaders/consumers for one k16 step s
    auto ldfrag = [&](const unsigned st, int s, unsigned ah[2][4],
                      unsigned alr[2][4], unsigned bh4[4][2],
                      unsigned bl4[4][2]) {
#pragma unroll
        for (int mt = 0; mt < 2; mt++) {
            unsigned ca = (unsigned)(((2 * s + achi) ^ arw[mt]) << 4);
            ldsm4(ah[mt], st + aoff[mt] + ca);
            if (SPLIT) ldsm4(alr[mt], st + 16384 + aoff[mt] + ca);
        }
#pragma unroll
        for (int g = 0; g < 2; g++) {
            unsigned cb = (unsigned)(((2 * s + bchi) ^ brw[g]) << 4);
            unsigned t[4];
            ldsm4(t, st + BOFF + boff[g] + cb);
            bh4[2 * g][0] = t[0]; bh4[2 * g][1] = t[1];
            bh4[2 * g + 1][0] = t[2]; bh4[2 * g + 1][1] = t[3];
            if (SPLIT) {
                ldsm4(t, st + BOFF + BSZ + boff[g] + cb);
                bl4[2 * g][0] = t[0]; bl4[2 * g][1] = t[1];
                bl4[2 * g + 1][0] = t[2]; bl4[2 * g + 1][1] = t[3];
            }
        }
    };

    float acc[2][4][4];
#pragma unroll
    for (int a = 0; a < 2; a++)
#pragma unroll
        for (int b = 0; b < 4; b++)
#pragma unroll
            for (int c = 0; c < 4; c++) acc[a][b][c] = 0.f;

    auto dommA = [&](unsigned ah[2][4], unsigned alr[2][4], unsigned bh4[4][2],
                     unsigned bl4[4][2]) {
#pragma unroll
        for (int mt = 0; mt < 2; mt++)
#pragma unroll
            for (int nt = 0; nt < 4; nt++) {
                mma_f32(acc[mt][nt], ah[mt], bh4[nt]);
                if (SPLIT) {
                    mma_f32(acc[mt][nt], ah[mt], bl4[nt]);
                    mma_f32(acc[mt][nt], alr[mt], bh4[nt]);
                }
            }
    };

    issue(0); CP_COMMIT();
    issue(1); CP_COMMIT();

    for (int c = 0; c < nc; c++) {
        CP_WAIT1();
        __syncthreads();
        const unsigned st = sb + (c & 1) * STG;
        // phase 0: s = 0,1 — load + compute
#pragma unroll
        for (int s = 0; s < 2; s++) {
            unsigned ah[2][4], alr[2][4], bh4[4][2], bl4[4][2];
            ldfrag(st, s, ah, alr, bh4, bl4);
            dommA(ah, alr, bh4, bl4);
        }
        // phase 1: s = 2,3 — load both, barrier, issue next, then compute
        unsigned ah2[2][2][4], alr2[2][2][4], bh2[2][4][2], bl2[2][4][2];
#pragma unroll
        for (int q = 0; q < 2; q++)
            ldfrag(st, 2 + q, ah2[q], alr2[q], bh2[q], bl2[q]);
        __syncthreads();
        if (c + 2 < nc) issue(c + 2);
        CP_COMMIT();   // unconditional: keeps wait_group 1 sound at the tail
#pragma unroll
        for (int q = 0; q < 2; q++) dommA(ah2[q], alr2[q], bh2[q], bl2[q]);
    }
    // pipeline smem is dead from here; epilogue staging reuses it.

    // epilogue
    Cf = Cf ? Cf + (ll)blockIdx.z * sC : (float*)0;
    Ch = Ch ? Ch + (ll)blockIdx.z * sC : (fp16*)0;
    Cl = Cl ? Cl + (ll)blockIdx.z * sC : (fp16*)0;
    const int mirror = sym && (n0 >= m0 + 128);
    fp16* Sh = (fp16*)smarr;               // [64][136] hi staging
    fp16* Sl = (fp16*)smarr + 64 * 136;    // [64][136] lo staging
    float* Sm = (float*)smarr;             // [64][132] fp32 mirror staging
#pragma unroll
    for (int mt = 0; mt < 2; mt++)
#pragma unroll
        for (int nt = 0; nt < 4; nt++)
#pragma unroll
            for (int h = 0; h < 2; h++) {
                int rt = wm * 32 + mt * 16 + (lane >> 2) + h * 8;
                int ct = wn * 32 + nt * 8 + ((lane & 3) << 1);
                int r = m0 + rt;
                int cc = n0 + ct;
                float raw0 = acc[mt][nt][h * 2], raw1 = acc[mt][nt][h * 2 + 1];
                float v0 = raw0, v1 = raw1;
                if (bias) { v0 += bias[cc]; v1 += bias[cc + 1]; }
                if (dist) {
                    int d0 = max(-11, min(11, cc - r));
                    int d1 = max(-11, min(11, cc + 1 - r));
                    v0 += dist[d0 + 11];
                    v1 += dist[d1 + 11];
                }
                if (relu) { v0 = fmaxf(v0, 0.f); v1 = fmaxf(v1, 0.f); }
                if (Cf) {
                    *(float2*)(Cf + (ll)r * ldc + cc) = make_float2(v0, v1);
                    if (mirror) {   // stage raw for coalesced mirrored write
                        Sm[ct * 132 + rt] = raw0;
                        Sm[(ct + 1) * 132 + rt] = raw1;
                    }
                }
                if (Ch) {
                    __half2 hv;
                    hv.x = __float2half_rn(v0);
                    hv.y = __float2half_rn(v1);
                    *(__half2*)(Ch + (ll)r * ldc + cc) = hv;
                    __half2 lv;
                    lv.x = __float2half_rn(v0 - __half2float(hv.x));
                    lv.y = __float2half_rn(v1 - __half2float(hv.y));
                    if (Cl) *(__half2*)(Cl + (ll)r * ldc + cc) = lv;
                    if (ChT) {   // stage transposed split copy
                        Sh[ct * 136 + rt] = hv.x;
                        Sh[(ct + 1) * 136 + rt] = hv.y;
                        Sl[ct * 136 + rt] = lv.x;
                        Sl[(ct + 1) * 136 + rt] = lv.y;
                    }
                }
            }

    if (ChT) {   // coalesced transposed writeback: 64 rows x 128 fp16
        __syncthreads();
        const int b = m0 >> 9, rrb = m0 & 511;
        const ll base = (ll)blockIdx.z * sTz + (ll)b * 524288 + rrb;
#pragma unroll
        for (int i = 0; i < 4; i++) {
            int idx = tid + i * 256;
            int row = idx >> 4, vec = idx & 15;
            uint4 vh = *(uint4*)(Sh + row * 136 + vec * 8);
            uint4 vl = *(uint4*)(Sl + row * 136 + vec * 8);
            ll o = base + (ll)(n0 + row) * 512 + vec * 8;
            *(uint4*)(ChT + o) = vh;
            *(uint4*)(ClT + o) = vl;
        }
    }
    if (mirror) {  // coalesced mirrored writeback with mirrored rel-bias
        __syncthreads();
#pragma unroll
        for (int i = 0; i < 8; i++) {
            int idx = tid + i * 256;
            int row = idx >> 5, vec = idx & 31;
            float4 v = *(float4*)(Sm + row * 132 + vec * 4);
            int cc = n0 + row;
            int rb = m0 + vec * 4;
            v.x += dist[max(-11, min(11, rb - cc)) + 11];
            v.y += dist[max(-11, min(11, rb + 1 - cc)) + 11];
            v.z += dist[max(-11, min(11, rb + 2 - cc)) + 11];
            v.w += dist[max(-11, min(11, rb + 3 - cc)) + 11];
            *(float4*)(Cf + (ll)cc * ldc + rb) = v;
        }
    }
}

// ---------------- prep / glue kernels ---------------------------------------
__global__ void ksplit(const float* __restrict__ x, fp16* __restrict__ h,
                       fp16* __restrict__ l, int n) {
    int i = blockIdx.x * 256 + threadIdx.x;
    if (i < n) {
        float v = x[i];
        fp16 a = __float2half_rn(v);
        h[i] = a;
        l[i] = __float2half_rn(v - __half2float(a));
    }
}

__global__ void kbias(const float* __restrict__ b0, const float* __restrict__ b1,
                      float* __restrict__ out) {
    int t = threadIdx.x;
    out[t] = b0[t];
    out[512 + t] = b1[t];
}

__global__ void kwtrans(const float* __restrict__ W, fp16* __restrict__ th,
                        fp16* __restrict__ tl, int Kd, int Nd) {
    __shared__ float t[32][33];
    int n0 = blockIdx.x * 32, k0 = blockIdx.y * 32;
    int tx = threadIdx.x, ty = threadIdx.y;
#pragma unroll
    for (int j = 0; j < 32; j += 8)
        t[ty + j][tx] = W[(ll)(k0 + ty + j) * Nd + n0 + tx];
    __syncthreads();
#pragma unroll
    for (int j = 0; j < 32; j += 8) {
        float v = t[tx][ty + j];
        fp16 a = __float2half_rn(v);
        ll o = (ll)(n0 + ty + j) * Kd + k0 + tx;
        th[o] = a;
        tl[o] = __float2half_rn(v - __half2float(a));
    }
}

__global__ void ktranspose_f(const float* __restrict__ in, float* __restrict__ out) {
    __shared__ float tile[32][33];
    ll base = (ll)blockIdx.z * 512 * 512;
    int x = blockIdx.x * 32 + threadIdx.x, y = blockIdx.y * 32 + threadIdx.y;
#pragma unroll
    for (int j = 0; j < 32; j += 8)
        tile[threadIdx.y + j][threadIdx.x] = in[base + (ll)(y + j) * 512 + x];
    __syncthreads();
    int ox = blockIdx.y * 32 + threadIdx.x, oy = blockIdx.x * 32 + threadIdx.y;
#pragma unroll
    for (int j = 0; j < 32; j += 8)
        out[base + (ll)(oy + j) * 512 + ox] = tile[threadIdx.x][threadIdx.y + j];
}

__global__ void ksmsplit(const float* __restrict__ X, fp16* __restrict__ H,
                         fp16* __restrict__ L) {
    const float* p = X + (ll)blockIdx.x * 512;
    fp16* ph = H + (ll)blockIdx.x * 512;
    fp16* pl = L + (ll)blockIdx.x * 512;
    int t = threadIdx.x;
    float a = p[t], b = p[t + 256];
    float m = fmaxf(a, b);
#pragma unroll
    for (int o = 16; o; o >>= 1) m = fmaxf(m, __shfl_xor_sync(~0u, m, o));
    __shared__ float smx[8], ssm[8];
    if ((t & 31) == 0) smx[t >> 5] = m;
    __syncthreads();
    float mm = smx[0];
#pragma unroll
    for (int i = 1; i < 8; i++) mm = fmaxf(mm, smx[i]);
    float ea = expf(a - mm), eb = expf(b - mm);
    float s = ea + eb;
#pragma unroll
    for (int o = 16; o; o >>= 1) s += __shfl_xor_sync(~0u, s, o);
    if ((t & 31) == 0) ssm[t >> 5] = s;
    __syncthreads();
    float tot = 0.f;
#pragma unroll
    for (int i = 0; i < 8; i++) tot += ssm[i];
    float inv = 1.f / tot;
    float va = ea * inv, vb = eb * inv;
    fp16 ha = __float2half_rn(va), hb = __float2half_rn(vb);
    ph[t] = ha;        pl[t] = __float2half_rn(va - __half2float(ha));
    ph[t + 256] = hb;  pl[t + 256] = __float2half_rn(vb - __half2float(hb));
}

__global__ void kreduce(const float* __restrict__ X, float* __restrict__ out) {
    int b = blockIdx.x, col = blockIdx.y * 128 + threadIdx.x;
    const float* p = X + (ll)b * 512 * 512 + col;
    float s = 0.f;
#pragma unroll 4
    for (int i = 0; i < 512; i++) s += p[(ll)i * 512];
    int bb = (b < 32) ? b : (b - 32);
    int off = (b < 32) ? 0 : 512;
    out[bb * 1024 + off + col] = s;
}

__global__ void kmlp(const float* __restrict__ A, const float* __restrict__ W,
                     const float* __restrict__ bias, float* __restrict__ out,
                     int K, int N) {
    int b = blockIdx.x, n = threadIdx.x;
    const float* a = A + (ll)b * K;
    float s = bias[n];
    for (int k = 0; k < K; k++) s = fmaf(a[k], W[(ll)k * N + n], s);
    out[(ll)b * N + n] = fmaxf(s, 0.f);
}

// ---------------- host ------------------------------------------------------
static void G(int split, const fp16* Ah, const fp16* Al, int lda, ll sA,
              const fp16* Bh, const fp16* Bl, int ldb, ll sB,
              float* Cf, fp16* Ch, fp16* Cl, int ldc, ll sC,
              const float* bias, ll sBias, int relu, const float* dist,
              int M, int N, int K, int nb, int bswap = 0, int sym = 0,
              fp16* ChT = nullptr, fp16* ClT = nullptr, ll sTz = 0) {
    dim3 g = sym ? dim3(20, 1, nb) : dim3(N / 64, M / 128, nb);
    if (split)
        tcgemm<1><<<g, 256, 2 * 49152>>>(Ah, Al, lda, sA, Bh, Bl, ldb, sB,
                                         Cf, Ch, Cl, ldc, sC, ChT, ClT, sTz,
                                         bias, sBias, relu, dist, K, bswap, sym);
    else
        tcgemm<0><<<g, 256, 2 * 24576>>>(Ah, Al, lda, sA, Bh, Bl, ldb, sB,
                                         Cf, Ch, Cl, ldc, sC, ChT, ClT, sTz,
                                         bias, sBias, relu, dist, K, bswap, sym);
}

extern "C" void kernel_launch(void* const* d_in, const int* in_sizes, int n_in,
                              void* d_out, int out_size) {
    const float* prem = (const float*)d_in[0];
    const float* hypo = (const float*)d_in[1];
    const float* Wpx = (const float*)d_in[4];  const float* bpx = (const float*)d_in[5];
    const float* Wpy = (const float*)d_in[6];  const float* bpy = (const float*)d_in[7];
    const float* dist = (const float*)d_in[8];
    const float* Ws1 = (const float*)d_in[9];  const float* bs1 = (const float*)d_in[10];
    const float* Ws2 = (const float*)d_in[11]; const float* bs2 = (const float*)d_in[12];
    const float* Wa1 = (const float*)d_in[13]; const float* ba1 = (const float*)d_in[14];
    const float* Wa2 = (const float*)d_in[15]; const float* ba2 = (const float*)d_in[16];
    const float* Wc1 = (const float*)d_in[17]; const float* bc1 = (const float*)d_in[18];
    const float* Wc2 = (const float*)d_in[19]; const float* bc2 = (const float*)d_in[20];
    const float* Wg1 = (const float*)d_in[21]; const float* bg1 = (const float*)d_in[22];
    const float* Wg2 = (const float*)d_in[23]; const float* bg2 = (const float*)d_in[24];
    float* out = (float*)d_out;

    fp16* hp;  float* fpp;
    cudaGetSymbolAddress((void**)&hp, g_fp16);
    cudaGetSymbolAddress((void**)&fpp, g_fp);
    cudaFuncSetAttribute(tcgemm<1>, cudaFuncAttributeMaxDynamicSharedMemorySize,
                         2 * 49152);
    cudaFuncSetAttribute(tcgemm<0>, cudaFuncAttributeMaxDynamicSharedMemorySize,
                         2 * 24576);

#define BP(o) (hp + (o))
    float* SB = fpp;
    float* ST = fpp + E1;
    float* RED = fpp + 2 * E1;
    float* AGG = RED + 32768;
    float* BB = AGG + 16384;

    const ll sS = 512LL * 512, sX = 512LL * 2048, sT = 1024LL * 512;
    dim3 tb(32, 8);

    // prep (launch index 5 = merged projection tcgemm<1>, for ncu -s 5 -c 1)
    ksplit<<<(int)(E1 / 256), 256>>>(prem, BP(O_IPH), BP(O_IPL), (int)E1);   // 0
    ksplit<<<(int)(E1 / 256), 256>>>(hypo, BP(O_IHH), BP(O_IHL), (int)E1);   // 1
    kbias<<<1, 512>>>(bpy, bpx, BB);                                         // 2
    kwtrans<<<dim3(16, 16), tb>>>(Wpy, BP(O_WPYH), BP(O_WPYL), 512, 512);    // 3
    kwtrans<<<dim3(16, 16), tb>>>(Wpx, BP(O_WPXH), BP(O_WPXL), 512, 512);    // 4

    // 1) merged projections (batch 2) + fused transposed copies -> PT/HT  // 5
    G(1, BP(O_IPH), BP(O_IPL), 512, E1, BP(O_WPYH), BP(O_WPYL), 512, W1,
      nullptr, BP(O_PXH), BP(O_PXL), 2048, E2, BB, 512, 0, nullptr,
      16384, 512, 512, 2, 0, 0, BP(O_PTH), BP(O_PTL), E3);

    // remaining weight prep
    kwtrans<<<dim3(16, 16), tb>>>(Ws1, BP(O_WS1H), BP(O_WS1L), 512, 512);
    kwtrans<<<dim3(16, 16), tb>>>(Ws2, BP(O_WS2H), BP(O_WS2L), 512, 512);
    kwtrans<<<dim3(16, 32), tb>>>(Wa1, BP(O_WA1H), BP(O_WA1L), 1024, 512);
    kwtrans<<<dim3(16, 16), tb>>>(Wa2, BP(O_WA2H), BP(O_WA2L), 512, 512);
    kwtrans<<<dim3(16, 64), tb>>>(Wc1, BP(O_WC1H), BP(O_WC1L), 2048, 512);
    kwtrans<<<dim3(16, 16), tb>>>(Wc2, BP(O_WC2H), BP(O_WC2L), 512, 512);

    // 2) self-attention merged: F|G = mlp2(X[:, :512]); SYMMETRIC scores;
    //    softmax; ctx with fused transposed copy
    G(1, BP(O_PXH), BP(O_PXL), 2048, 0, BP(O_WS1H), BP(O_WS1L), 512, 0,
      nullptr, BP(O_TH), BP(O_TL), 512, 0, bs1, 0, 1, nullptr, 32768, 512, 512, 1);
    G(1, BP(O_TH), BP(O_TL), 512, 0, BP(O_WS2H), BP(O_WS2L), 512, 0,
      nullptr, BP(O_FH), BP(O_FL), 512, 0, bs2, 0, 1, nullptr, 32768, 512, 512, 1);
    G(1, BP(O_FH), BP(O_FL), 512, sS, BP(O_FH), BP(O_FL), 512, sS,
      SB, nullptr, nullptr, 512, sS, nullptr, 0, 0, dist, 512, 512, 512, 64,
      0, 1);
    ksmsplit<<<32768, 256>>>(SB, BP(O_P1H), BP(O_P1L));
    G(1, BP(O_P1H), BP(O_P1L), 512, sS, BP(O_PTH), BP(O_PTL), 512, sT,
      nullptr, BP(O_PXH) + 512, BP(O_PXL) + 512, 2048, sX,
      nullptr, 0, 0, nullptr, 512, 512, 512, 64, 0, 0,
      BP(O_PTH) + 512 * 512, BP(O_PTL) + 512 * 512, sT);

    // 3) cross-attention MLPs merged (K=1024): F|G = gp|gh
    G(1, BP(O_PXH), BP(O_PXL), 2048, 0, BP(O_WA1H), BP(O_WA1L), 1024, 0,
      nullptr, BP(O_TH), BP(O_TL), 512, 0, ba1, 0, 1, nullptr, 32768, 512, 1024, 1);
    G(1, BP(O_TH), BP(O_TL), 512, 0, BP(O_WA2H), BP(O_WA2L), 512, 0,
      nullptr, BP(O_FH), BP(O_FL), 512, 0, ba2, 0, 1, nullptr, 32768, 512, 512, 1);

    // 4) sim = gp@gh^T (32 batches); simT via fp32 transpose; softmax both
    G(1, BP(O_FH), BP(O_FL), 512, sS, BP(O_GH), BP(O_GL), 512, sS,
      SB, nullptr, nullptr, 512, sS, nullptr, 0, 0, nullptr, 512, 512, 512, 32);
    ktranspose_f<<<dim3(16, 16, 32), tb>>>(SB, ST);
    ksmsplit<<<32768, 256>>>(SB, BP(O_P1H), BP(O_P1L));   // [p2h | h2p]

    // 5) attended (1-MMA tier): X cols [1024:2048)
    G(0, BP(O_P1H), nullptr, 512, sS, BP(O_PTH), nullptr, 512, sT,
      nullptr, BP(O_PXH) + 1024, nullptr, 2048, sX,
      nullptr, 0, 0, nullptr, 512, 1024, 512, 64, 1);

    // 6) compare merged (1-MMA tier) + pooled sums
    G(0, BP(O_PXH), nullptr, 2048, 0, BP(O_WC1H), nullptr, 2048, 0,
      nullptr, BP(O_TH), nullptr, 512, 0, bc1, 0, 1, nullptr, 32768, 512, 2048, 1);
    G(0, BP(O_TH), nullptr, 512, 0, BP(O_WC2H), nullptr, 512, 0,
      SB, nullptr, nullptr, 512, 0, bc2, 0, 1, nullptr, 32768, 512, 512, 1);
    kreduce<<<dim3(64, 4), 128>>>(SB, RED);

    // 7) aggregate MLP (fp32)
    kmlp<<<32, 512>>>(RED, Wg1, bg1, AGG, 1024, 512);
    kmlp<<<32, 512>>>(AGG, Wg2, bg2, out, 512, 512);
}

// round 17
// speedup vs baseline: 1.0657x; 1.0657x over previous
#include <cuda_runtime.h>
#include <cuda_fp16.h>

// ============================================================================
// DecomposableAttentionEncoder on GB300 (sm_103a), compute_103-safe.
// GEMMs via warp-level mma.sync fp16, two precision tiers:
//   SPLIT=1: x=hi+lo fp16; A@B ~= AhBh+AhBl+AlBh, fp32 acc (3 MMA)
//   SPLIT=0: pure fp16-hi, 1 MMA (GEMMs strictly downstream of all softmaxes)
// Tile 128(M)x64(N), 256 threads, K-chunk 64, 2-stage cp.async, 2 CTAs/SM,
// unconditional tail commit (r11 race fix). Warp grid 4x2 (r15, ldsm-balanced).
// r12/r13: symmetric self-scores + smem-staged coalesced mirror; fused,
//          staged transposed split outputs.
// r17: mainloop reverted to the r15 form (r16 barrier-shadow spilled regs and
//      regressed); ksplit vectorized (float4/half2, 4 elem/thread).
// ============================================================================

typedef long long ll;
typedef __half fp16;

// ---------------- static pools (element counts, fp16) ------------------------
#define E1 8388608LL            // 32*512*512
#define E2 33554432LL           // 32*512*2048
#define E3 16777216LL           // 32*1024*512
#define W1 262144LL
#define W2 524288LL
#define W3 1048576LL
#define O_IPH 0LL
#define O_IHH (O_IPH+E1)
#define O_IPL (O_IHH+E1)
#define O_IHL (O_IPL+E1)
#define O_PXH (O_IHL+E1)
#define O_HXH (O_PXH+E2)
#define O_PXL (O_HXH+E2)
#define O_HXL (O_PXL+E2)
#define O_PTH (O_HXL+E2)
#define O_HTH (O_PTH+E3)
#define O_PTL (O_HTH+E3)
#define O_HTL (O_PTL+E3)
#define O_FH  (O_HTL+E3)
#define O_GH  (O_FH+E1)
#define O_FL  (O_GH+E1)
#define O_GL  (O_FL+E1)
#define O_TH  (O_GL+E1)
#define O_TL  (O_TH+2*E1)
#define O_P1H (O_TL+2*E1)
#define O_P1L (O_P1H+2*E1)
#define O_WPYH (O_P1L+2*E1)
#define O_WPXH (O_WPYH+W1)
#define O_WPYL (O_WPXH+W1)
#define O_WPXL (O_WPYL+W1)
#define O_WS1H (O_WPXL+W1)
#define O_WS1L (O_WS1H+W1)
#define O_WS2H (O_WS1L+W1)
#define O_WS2L (O_WS2H+W1)
#define O_WA2H (O_WS2L+W1)
#define O_WA2L (O_WA2H+W1)
#define O_WC2H (O_WA2L+W1)
#define O_WC2L (O_WC2H+W1)
#define O_WA1H (O_WC2L+W1)
#define O_WA1L (O_WA1H+W2)
#define O_WC1H (O_WA1L+W2)
#define O_WC1L (O_WC1H+W3)
#define FP16_TOTAL (O_WC1L+W3)

__device__ fp16 g_fp16[FP16_TOTAL];
__device__ float g_fp[2 * E1 + 32768 + 16384 + 1024];   // SB|ST, RED, AGG, BB

// triangular super-tile tables (4x4 upper triangle incl. diagonal, 10 tiles)
__constant__ int c_smt[10] = {0, 0, 0, 0, 1, 1, 1, 2, 2, 3};
__constant__ int c_snt[10] = {0, 1, 2, 3, 1, 2, 3, 2, 3, 3};

// ---------------- PTX helpers -----------------------------------------------
__device__ __forceinline__ unsigned smem_u32(const void* p) {
    unsigned a;
    asm("{ .reg .u64 t; cvta.to.shared.u64 t, %1; cvt.u32.u64 %0, t; }"
        : "=r"(a) : "l"(p));
    return a;
}
__device__ __forceinline__ void cp16(unsigned dst, const void* src) {
    asm volatile("cp.async.cg.shared.global [%0], [%1], 16;"
                 ::"r"(dst), "l"(src) : "memory");
}
#define CP_COMMIT() asm volatile("cp.async.commit_group;" ::: "memory")
#define CP_WAIT1() asm volatile("cp.async.wait_group 1;" ::: "memory")

__device__ __forceinline__ void ldsm4(unsigned r[4], unsigned addr) {
    asm volatile("ldmatrix.sync.aligned.m8n8.x4.shared.b16 {%0,%1,%2,%3}, [%4];"
                 : "=r"(r[0]), "=r"(r[1]), "=r"(r[2]), "=r"(r[3]) : "r"(addr));
}
__device__ __forceinline__ void mma_f32(float c[4], const unsigned a[4],
                                        const unsigned b[2]) {
    asm volatile(
        "mma.sync.aligned.m16n8k16.row.col.f32.f16.f16.f32 "
        "{%0,%1,%2,%3}, {%4,%5,%6,%7}, {%8,%9}, {%0,%1,%2,%3};"
        : "+f"(c[0]), "+f"(c[1]), "+f"(c[2]), "+f"(c[3])
        : "r"(a[0]), "r"(a[1]), "r"(a[2]), "r"(a[3]), "r"(b[0]), "r"(b[1]));
}

// ---------------- HMMA GEMM (128x64 tile, occ 2, sym/fuse, staged) -----------
// C[M,N] = act( A @ B^T + bias (+dist relbias) ), 256 threads.
// Warp grid 4(M)x2(N): warp tile 32x32, ldsm-balanced.
// sym=1: triangular super-tiles; above-diagonal tiles also emit the mirrored
//        fp32 tile (raw + mirrored dist), staged + coalesced.
// ChT/ClT: transposed split fp16 outputs, staged + coalesced.
template <int SPLIT>
__global__ void __launch_bounds__(256, 2)
tcgemm(const fp16* __restrict__ Ah, const fp16* __restrict__ Al, int lda, ll sA,
       const fp16* __restrict__ Bh, const fp16* __restrict__ Bl, int ldb, ll sB,
       float* Cf, fp16* Ch, fp16* Cl, int ldc, ll sC,
       fp16* ChT, fp16* ClT, ll sTz,
       const float* __restrict__ bias, ll sBias, int relu,
       const float* __restrict__ dist, int K, int bswap, int sym) {
    constexpr unsigned BOFF = SPLIT ? 32768u : 16384u;
    constexpr unsigned BSZ = 8192u;
    constexpr unsigned STG = SPLIT ? 49152u : 24576u;
    extern __shared__ char smarr[];
    const unsigned sb = smem_u32(smarr);
    const int tid = threadIdx.x, lane = tid & 31, wid = tid >> 5;
    const int wm = wid >> 1, wn = wid & 1;   // warp tile 32(M) x 32(N)
    int m0, n0;
    if (sym) {
        int t = blockIdx.x >> 1;
        m0 = c_smt[t] * 128;
        n0 = c_snt[t] * 128 + (blockIdx.x & 1) * 64;
    } else {
        m0 = blockIdx.y * 128;
        n0 = blockIdx.x * 64;
    }
    const int bz = bswap ? ((int)blockIdx.z ^ 32) : (int)blockIdx.z;
    Ah += (ll)blockIdx.z * sA;
    Bh += (ll)bz * sB;
    if (SPLIT) { Al += (ll)blockIdx.z * sA; Bl += (ll)bz * sB; }
    if (bias) bias += (ll)blockIdx.z * sBias;

    const int nc = K >> 6;

    unsigned aoff[2];
    int arw[2];
#pragma unroll
    for (int mt = 0; mt < 2; mt++) {
        int r = wm * 32 + mt * 16 + (lane & 15);
        aoff[mt] = r * 128;
        arw[mt] = r & 7;
    }
    unsigned boff[2];
    int brw[2];
#pragma unroll
    for (int g = 0; g < 2; g++) {
        int r = wn * 32 + g * 16 + (lane & 7) + (((lane >> 4) & 1) << 3);
        boff[g] = r * 128;
        brw[g] = r & 7;
    }
    const int achi = (lane >> 4) & 1;
    const int bchi = (lane >> 3) & 1;

    auto issue = [&](int c) {
        const int kc = c * 64;
        const unsigned st = sb + (c & 1) * STG;
#pragma unroll
        for (int i = 0; i < 4; i++) {
            int idx = tid + i * 256;
            int r = idx >> 3, ck = idx & 7;
            unsigned sw = (unsigned)(r * 128 + ((ck ^ (r & 7)) << 4));
            const ll ao = (ll)(m0 + r) * lda + kc + ck * 8;
            cp16(st + sw, Ah + ao);
            if (SPLIT) cp16(st + 16384 + sw, Al + ao);
        }
#pragma unroll
        for (int i = 0; i < 2; i++) {
            int idx = tid + i * 256;
            int r = idx >> 3, ck = idx & 7;
            unsigned sw = (unsigned)(r * 128 + ((ck ^ (r & 7)) << 4));
            const ll bo = (ll)(n0 + r) * ldb + kc + ck * 8;
            cp16(st + BOFF + sw, Bh + bo);
            if (SPLIT) cp16(st + BOFF + BSZ + sw, Bl + bo);
        }
    };

    float acc[2][4][4];
#pragma unroll
    for (int a = 0; a < 2; a++)
#pragma unroll
        for (int b = 0; b < 4; b++)
#pragma unroll
            for (int c = 0; c < 4; c++) acc[a][b][c] = 0.f;

    issue(0); CP_COMMIT();
    issue(1); CP_COMMIT();

    for (int c = 0; c < nc; c++) {
        CP_WAIT1();
        __syncthreads();
        const unsigned st = sb + (c & 1) * STG;
#pragma unroll
        for (int s = 0; s < 4; s++) {
            unsigned ah[2][4], alr[2][4];
#pragma unroll
            for (int mt = 0; mt < 2; mt++) {
                unsigned ca = (unsigned)(((2 * s + achi) ^ arw[mt]) << 4);
                ldsm4(ah[mt], st + aoff[mt] + ca);
                if (SPLIT) ldsm4(alr[mt], st + 16384 + aoff[mt] + ca);
            }
            unsigned bh4[4][2], bl4[4][2];
#pragma unroll
            for (int g = 0; g < 2; g++) {
                unsigned cb = (unsigned)(((2 * s + bchi) ^ brw[g]) << 4);
                unsigned t[4];
                ldsm4(t, st + BOFF + boff[g] + cb);
                bh4[2 * g][0] = t[0]; bh4[2 * g][1] = t[1];
                bh4[2 * g + 1][0] = t[2]; bh4[2 * g + 1][1] = t[3];
                if (SPLIT) {
                    ldsm4(t, st + BOFF + BSZ + boff[g] + cb);
                    bl4[2 * g][0] = t[0]; bl4[2 * g][1] = t[1];
                    bl4[2 * g + 1][0] = t[2]; bl4[2 * g + 1][1] = t[3];
                }
            }
#pragma unroll
            for (int mt = 0; mt < 2; mt++)
#pragma unroll
                for (int nt = 0; nt < 4; nt++) {
                    mma_f32(acc[mt][nt], ah[mt], bh4[nt]);
                    if (SPLIT) {
                        mma_f32(acc[mt][nt], ah[mt], bl4[nt]);
                        mma_f32(acc[mt][nt], alr[mt], bh4[nt]);
                    }
                }
        }
        __syncthreads();
        if (c + 2 < nc) issue(c + 2);
        CP_COMMIT();   // unconditional: keeps wait_group 1 sound at the tail
    }
    // pipeline smem is dead from here; epilogue staging reuses it.

    // epilogue
    Cf = Cf ? Cf + (ll)blockIdx.z * sC : (float*)0;
    Ch = Ch ? Ch + (ll)blockIdx.z * sC : (fp16*)0;
    Cl = Cl ? Cl + (ll)blockIdx.z * sC : (fp16*)0;
    const int mirror = sym && (n0 >= m0 + 128);
    fp16* Sh = (fp16*)smarr;               // [64][136] hi staging
    fp16* Sl = (fp16*)smarr + 64 * 136;    // [64][136] lo staging
    float* Sm = (float*)smarr;             // [64][132] fp32 mirror staging
#pragma unroll
    for (int mt = 0; mt < 2; mt++)
#pragma unroll
        for (int nt = 0; nt < 4; nt++)
#pragma unroll
            for (int h = 0; h < 2; h++) {
                int rt = wm * 32 + mt * 16 + (lane >> 2) + h * 8;
                int ct = wn * 32 + nt * 8 + ((lane & 3) << 1);
                int r = m0 + rt;
                int cc = n0 + ct;
                float raw0 = acc[mt][nt][h * 2], raw1 = acc[mt][nt][h * 2 + 1];
                float v0 = raw0, v1 = raw1;
                if (bias) { v0 += bias[cc]; v1 += bias[cc + 1]; }
                if (dist) {
                    int d0 = max(-11, min(11, cc - r));
                    int d1 = max(-11, min(11, cc + 1 - r));
                    v0 += dist[d0 + 11];
                    v1 += dist[d1 + 11];
                }
                if (relu) { v0 = fmaxf(v0, 0.f); v1 = fmaxf(v1, 0.f); }
                if (Cf) {
                    *(float2*)(Cf + (ll)r * ldc + cc) = make_float2(v0, v1);
                    if (mirror) {   // stage raw for coalesced mirrored write
                        Sm[ct * 132 + rt] = raw0;
                        Sm[(ct + 1) * 132 + rt] = raw1;
                    }
                }
                if (Ch) {
                    __half2 hv;
                    hv.x = __float2half_rn(v0);
                    hv.y = __float2half_rn(v1);
                    *(__half2*)(Ch + (ll)r * ldc + cc) = hv;
                    __half2 lv;
                    lv.x = __float2half_rn(v0 - __half2float(hv.x));
                    lv.y = __float2half_rn(v1 - __half2float(hv.y));
                    if (Cl) *(__half2*)(Cl + (ll)r * ldc + cc) = lv;
                    if (ChT) {   // stage transposed split copy
                        Sh[ct * 136 + rt] = hv.x;
                        Sh[(ct + 1) * 136 + rt] = hv.y;
                        Sl[ct * 136 + rt] = lv.x;
                        Sl[(ct + 1) * 136 + rt] = lv.y;
                    }
                }
            }

    if (ChT) {   // coalesced transposed writeback: 64 rows x 128 fp16
        __syncthreads();
        const int b = m0 >> 9, rrb = m0 & 511;
        const ll base = (ll)blockIdx.z * sTz + (ll)b * 524288 + rrb;
#pragma unroll
        for (int i = 0; i < 4; i++) {
            int idx = tid + i * 256;
            int row = idx >> 4, vec = idx & 15;
            uint4 vh = *(uint4*)(Sh + row * 136 + vec * 8);
            uint4 vl = *(uint4*)(Sl + row * 136 + vec * 8);
            ll o = base + (ll)(n0 + row) * 512 + vec * 8;
            *(uint4*)(ChT + o) = vh;
            *(uint4*)(ClT + o) = vl;
        }
    }
    if (mirror) {  // coalesced mirrored writeback with mirrored rel-bias
        __syncthreads();
#pragma unroll
        for (int i = 0; i < 8; i++) {
            int idx = tid + i * 256;
            int row = idx >> 5, vec = idx & 31;
            float4 v = *(float4*)(Sm + row * 132 + vec * 4);
            int cc = n0 + row;
            int rb = m0 + vec * 4;
            v.x += dist[max(-11, min(11, rb - cc)) + 11];
            v.y += dist[max(-11, min(11, rb + 1 - cc)) + 11];
            v.z += dist[max(-11, min(11, rb + 2 - cc)) + 11];
            v.w += dist[max(-11, min(11, rb + 3 - cc)) + 11];
            *(float4*)(Cf + (ll)cc * ldc + rb) = v;
        }
    }
}

// ---------------- prep / glue kernels ---------------------------------------
// vectorized split: 4 elems/thread (float4 in, half2 out)
__global__ void ksplit(const float* __restrict__ x, fp16* __restrict__ h,
                       fp16* __restrict__ l, int n) {
    int i = (blockIdx.x * 256 + threadIdx.x) * 4;
    if (i < n) {
        float4 v = *(const float4*)(x + i);
        __half2 h0, h1, l0, l1;
        h0.x = __float2half_rn(v.x);
        h0.y = __float2half_rn(v.y);
        h1.x = __float2half_rn(v.z);
        h1.y = __float2half_rn(v.w);
        l0.x = __float2half_rn(v.x - __half2float(h0.x));
        l0.y = __float2half_rn(v.y - __half2float(h0.y));
        l1.x = __float2half_rn(v.z - __half2float(h1.x));
        l1.y = __float2half_rn(v.w - __half2float(h1.y));
        *(__half2*)(h + i) = h0;
        *(__half2*)(h + i + 2) = h1;
        *(__half2*)(l + i) = l0;
        *(__half2*)(l + i + 2) = l1;
    }
}

__global__ void kbias(const float* __restrict__ b0, const float* __restrict__ b1,
                      float* __restrict__ out) {
    int t = threadIdx.x;
    out[t] = b0[t];
    out[512 + t] = b1[t];
}

__global__ void kwtrans(const float* __restrict__ W, fp16* __restrict__ th,
                        fp16* __restrict__ tl, int Kd, int Nd) {
    __shared__ float t[32][33];
    int n0 = blockIdx.x * 32, k0 = blockIdx.y * 32;
    int tx = threadIdx.x, ty = threadIdx.y;
#pragma unroll
    for (int j = 0; j < 32; j += 8)
        t[ty + j][tx] = W[(ll)(k0 + ty + j) * Nd + n0 + tx];
    __syncthreads();
#pragma unroll
    for (int j = 0; j < 32; j += 8) {
        float v = t[tx][ty + j];
        fp16 a = __float2half_rn(v);
        ll o = (ll)(n0 + ty + j) * Kd + k0 + tx;
        th[o] = a;
        tl[o] = __float2half_rn(v - __half2float(a));
    }
}

__global__ void ktranspose_f(const float* __restrict__ in, float* __restrict__ out) {
    __shared__ float tile[32][33];
    ll base = (ll)blockIdx.z * 512 * 512;
    int x = blockIdx.x * 32 + threadIdx.x, y = blockIdx.y * 32 + threadIdx.y;
#pragma unroll
    for (int j = 0; j < 32; j += 8)
        tile[threadIdx.y + j][threadIdx.x] = in[base + (ll)(y + j) * 512 + x];
    __syncthreads();
    int ox = blockIdx.y * 32 + threadIdx.x, oy = blockIdx.x * 32 + threadIdx.y;
#pragma unroll
    for (int j = 0; j < 32; j += 8)
        out[base + (ll)(oy + j) * 512 + ox] = tile[threadIdx.x][threadIdx.y + j];
}

__global__ void ksmsplit(const float* __restrict__ X, fp16* __restrict__ H,
                         fp16* __restrict__ L) {
    const float* p = X + (ll)blockIdx.x * 512;
    fp16* ph = H + (ll)blockIdx.x * 512;
    fp16* pl = L + (ll)blockIdx.x * 512;
    int t = threadIdx.x;
    float a = p[t], b = p[t + 256];
    float m = fmaxf(a, b);
#pragma unroll
    for (int o = 16; o; o >>= 1) m = fmaxf(m, __shfl_xor_sync(~0u, m, o));
    __shared__ float smx[8], ssm[8];
    if ((t & 31) == 0) smx[t >> 5] = m;
    __syncthreads();
    float mm = smx[0];
#pragma unroll
    for (int i = 1; i < 8; i++) mm = fmaxf(mm, smx[i]);
    float ea = expf(a - mm), eb = expf(b - mm);
    float s = ea + eb;
#pragma unroll
    for (int o = 16; o; o >>= 1) s += __shfl_xor_sync(~0u, s, o);
    if ((t & 31) == 0) ssm[t >> 5] = s;
    __syncthreads();
    float tot = 0.f;
#pragma unroll
    for (int i = 0; i < 8; i++) tot += ssm[i];
    float inv = 1.f / tot;
    float va = ea * inv, vb = eb * inv;
    fp16 ha = __float2half_rn(va), hb = __float2half_rn(vb);
    ph[t] = ha;        pl[t] = __float2half_rn(va - __half2float(ha));
    ph[t + 256] = hb;  pl[t + 256] = __float2half_rn(vb - __half2float(hb));
}

__global__ void kreduce(const float* __restrict__ X, float* __restrict__ out) {
    int b = blockIdx.x, col = blockIdx.y * 128 + threadIdx.x;
    const float* p = X + (ll)b * 512 * 512 + col;
    float s = 0.f;
#pragma unroll 4
    for (int i = 0; i < 512; i++) s += p[(ll)i * 512];
    int bb = (b < 32) ? b : (b - 32);
    int off = (b < 32) ? 0 : 512;
    out[bb * 1024 + off + col] = s;
}

__global__ void kmlp(const float* __restrict__ A, const float* __restrict__ W,
                     const float* __restrict__ bias, float* __restrict__ out,
                     int K, int N) {
    int b = blockIdx.x, n = threadIdx.x;
    const float* a = A + (ll)b * K;
    float s = bias[n];
    for (int k = 0; k < K; k++) s = fmaf(a[k], W[(ll)k * N + n], s);
    out[(ll)b * N + n] = fmaxf(s, 0.f);
}

// ---------------- host ------------------------------------------------------
static void G(int split, const fp16* Ah, const fp16* Al, int lda, ll sA,
              const fp16* Bh, const fp16* Bl, int ldb, ll sB,
              float* Cf, fp16* Ch, fp16* Cl, int ldc, ll sC,
              const float* bias, ll sBias, int relu, const float* dist,
              int M, int N, int K, int nb, int bswap = 0, int sym = 0,
              fp16* ChT = nullptr, fp16* ClT = nullptr, ll sTz = 0) {
    dim3 g = sym ? dim3(20, 1, nb) : dim3(N / 64, M / 128, nb);
    if (split)
        tcgemm<1><<<g, 256, 2 * 49152>>>(Ah, Al, lda, sA, Bh, Bl, ldb, sB,
                                         Cf, Ch, Cl, ldc, sC, ChT, ClT, sTz,
                                         bias, sBias, relu, dist, K, bswap, sym);
    else
        tcgemm<0><<<g, 256, 2 * 24576>>>(Ah, Al, lda, sA, Bh, Bl, ldb, sB,
                                         Cf, Ch, Cl, ldc, sC, ChT, ClT, sTz,
                                         bias, sBias, relu, dist, K, bswap, sym);
}

extern "C" void kernel_launch(void* const* d_in, const int* in_sizes, int n_in,
                              void* d_out, int out_size) {
    const float* prem = (const float*)d_in[0];
    const float* hypo = (const float*)d_in[1];
    const float* Wpx = (const float*)d_in[4];  const float* bpx = (const float*)d_in[5];
    const float* Wpy = (const float*)d_in[6];  const float* bpy = (const float*)d_in[7];
    const float* dist = (const float*)d_in[8];
    const float* Ws1 = (const float*)d_in[9];  const float* bs1 = (const float*)d_in[10];
    const float* Ws2 = (const float*)d_in[11]; const float* bs2 = (const float*)d_in[12];
    const float* Wa1 = (const float*)d_in[13]; const float* ba1 = (const float*)d_in[14];
    const float* Wa2 = (const float*)d_in[15]; const float* ba2 = (const float*)d_in[16];
    const float* Wc1 = (const float*)d_in[17]; const float* bc1 = (const float*)d_in[18];
    const float* Wc2 = (const float*)d_in[19]; const float* bc2 = (const float*)d_in[20];
    const float* Wg1 = (const float*)d_in[21]; const float* bg1 = (const float*)d_in[22];
    const float* Wg2 = (const float*)d_in[23]; const float* bg2 = (const float*)d_in[24];
    float* out = (float*)d_out;

    fp16* hp;  float* fpp;
    cudaGetSymbolAddress((void**)&hp, g_fp16);
    cudaGetSymbolAddress((void**)&fpp, g_fp);
    cudaFuncSetAttribute(tcgemm<1>, cudaFuncAttributeMaxDynamicSharedMemorySize,
                         2 * 49152);
    cudaFuncSetAttribute(tcgemm<0>, cudaFuncAttributeMaxDynamicSharedMemorySize,
                         2 * 24576);

#define BP(o) (hp + (o))
    float* SB = fpp;
    float* ST = fpp + E1;
    float* RED = fpp + 2 * E1;
    float* AGG = RED + 32768;
    float* BB = AGG + 16384;

    const ll sS = 512LL * 512, sX = 512LL * 2048, sT = 1024LL * 512;
    dim3 tb(32, 8);

    // prep (launch index 5 = merged projection tcgemm<1>, for ncu -s 5 -c 1)
    ksplit<<<(int)(E1 / 1024), 256>>>(prem, BP(O_IPH), BP(O_IPL), (int)E1);  // 0
    ksplit<<<(int)(E1 / 1024), 256>>>(hypo, BP(O_IHH), BP(O_IHL), (int)E1);  // 1
    kbias<<<1, 512>>>(bpy, bpx, BB);                                         // 2
    kwtrans<<<dim3(16, 16), tb>>>(Wpy, BP(O_WPYH), BP(O_WPYL), 512, 512);    // 3
    kwtrans<<<dim3(16, 16), tb>>>(Wpx, BP(O_WPXH), BP(O_WPXL), 512, 512);    // 4

    // 1) merged projections (batch 2) + fused transposed copies -> PT/HT  // 5
    G(1, BP(O_IPH), BP(O_IPL), 512, E1, BP(O_WPYH), BP(O_WPYL), 512, W1,
      nullptr, BP(O_PXH), BP(O_PXL), 2048, E2, BB, 512, 0, nullptr,
      16384, 512, 512, 2, 0, 0, BP(O_PTH), BP(O_PTL), E3);

    // remaining weight prep
    kwtrans<<<dim3(16, 16), tb>>>(Ws1, BP(O_WS1H), BP(O_WS1L), 512, 512);
    kwtrans<<<dim3(16, 16), tb>>>(Ws2, BP(O_WS2H), BP(O_WS2L), 512, 512);
    kwtrans<<<dim3(16, 32), tb>>>(Wa1, BP(O_WA1H), BP(O_WA1L), 1024, 512);
    kwtrans<<<dim3(16, 16), tb>>>(Wa2, BP(O_WA2H), BP(O_WA2L), 512, 512);
    kwtrans<<<dim3(16, 64), tb>>>(Wc1, BP(O_WC1H), BP(O_WC1L), 2048, 512);
    kwtrans<<<dim3(16, 16), tb>>>(Wc2, BP(O_WC2H), BP(O_WC2L), 512, 512);

    // 2) self-attention merged: F|G = mlp2(X[:, :512]); SYMMETRIC scores;
    //    softmax; ctx with fused transposed copy
    G(1, BP(O_PXH), BP(O_PXL), 2048, 0, BP(O_WS1H), BP(O_WS1L), 512, 0,
      nullptr, BP(O_TH), BP(O_TL), 512, 0, bs1, 0, 1, nullptr, 32768, 512, 512, 1);
    G(1, BP(O_TH), BP(O_TL), 512, 0, BP(O_WS2H), BP(O_WS2L), 512, 0,
      nullptr, BP(O_FH), BP(O_FL), 512, 0, bs2, 0, 1, nullptr, 32768, 512, 512, 1);
    G(1, BP(O_FH), BP(O_FL), 512, sS, BP(O_FH), BP(O_FL), 512, sS,
      SB, nullptr, nullptr, 512, sS, nullptr, 0, 0, dist, 512, 512, 512, 64,
      0, 1);
    ksmsplit<<<32768, 256>>>(SB, BP(O_P1H), BP(O_P1L));
    G(1, BP(O_P1H), BP(O_P1L), 512, sS, BP(O_PTH), BP(O_PTL), 512, sT,
      nullptr, BP(O_PXH) + 512, BP(O_PXL) + 512, 2048, sX,
      nullptr, 0, 0, nullptr, 512, 512, 512, 64, 0, 0,
      BP(O_PTH) + 512 * 512, BP(O_PTL) + 512 * 512, sT);

    // 3) cross-attention MLPs merged (K=1024): F|G = gp|gh
    G(1, BP(O_PXH), BP(O_PXL), 2048, 0, BP(O_WA1H), BP(O_WA1L), 1024, 0,
      nullptr, BP(O_TH), BP(O_TL), 512, 0, ba1, 0, 1, nullptr, 32768, 512, 1024, 1);
    G(1, BP(O_TH), BP(O_TL), 512, 0, BP(O_WA2H), BP(O_WA2L), 512, 0,
      nullptr, BP(O_FH), BP(O_FL), 512, 0, ba2, 0, 1, nullptr, 32768, 512, 512, 1);

    // 4) sim = gp@gh^T (32 batches); simT via fp32 transpose; softmax both
    G(1, BP(O_FH), BP(O_FL), 512, sS, BP(O_GH), BP(O_GL), 512, sS,
      SB, nullptr, nullptr, 512, sS, nullptr, 0, 0, nullptr, 512, 512, 512, 32);
    ktranspose_f<<<dim3(16, 16, 32), tb>>>(SB, ST);
    ksmsplit<<<32768, 256>>>(SB, BP(O_P1H), BP(O_P1L));   // [p2h | h2p]

    // 5) attended (1-MMA tier): X cols [1024:2048)
    G(0, BP(O_P1H), nullptr, 512, sS, BP(O_PTH), nullptr, 512, sT,
      nullptr, BP(O_PXH) + 1024, nullptr, 2048, sX,
      nullptr, 0, 0, nullptr, 512, 1024, 512, 64, 1);

    // 6) compare merged (1-MMA tier) + pooled sums
    G(0, BP(O_PXH), nullptr, 2048, 0, BP(O_WC1H), nullptr, 2048, 0,
      nullptr, BP(O_TH), nullptr, 512, 0, bc1, 0, 1, nullptr, 32768, 512, 2048, 1);
    G(0, BP(O_TH), nullptr, 512, 0, BP(O_WC2H), nullptr, 512, 0,
      SB, nullptr, nullptr, 512, 0, bc2, 0, 1, nullptr, 32768, 512, 512, 1);
    kreduce<<<dim3(64, 4), 128>>>(SB, RED);

    // 7) aggregate MLP (fp32)
    kmlp<<<32, 512>>>(RED, Wg1, bg1, AGG, 1024, 512);
    kmlp<<<32, 512>>>(AGG, Wg2, bg2, out, 512, 512);
}